// round 12
// baseline (speedup 1.0000x reference)
#include <cuda_runtime.h>
#include <cuda_bf16.h>
#include <mma.h>
#include <math.h>
#include <stdint.h>

using namespace nvcuda;

#define B_   4
#define S_   256
#define V_   64
#define LP1_ 11
#define H_   128
#define NH_  8
#define DH_  16
#define NL_  3
#define M_   (B_*S_)   // 1024

// ---------------- scratch (device globals; no allocation) ----------------
__device__ float g_adjT[V_*LP1_*V_];
__device__ float g_z [M_*V_*H_];
__device__ float g_z2[M_*V_*H_];
__device__ float g_qkv[3*M_*V_*H_];
__device__ __align__(16) __nv_bfloat16 g_whi[7*V_*H_*H_];
__device__ __align__(16) __nv_bfloat16 g_wlo[7*V_*H_*H_];

// ---------------- pack helpers --------------------------------------------
__device__ __forceinline__ uint32_t pkrn(float x, float y) {
    __nv_bfloat162 h = __floats2bfloat162_rn(x, y);
    return *(uint32_t*)&h;
}
__device__ __forceinline__ uint32_t pklo(float x, float y, uint32_t hi) {
    __nv_bfloat162 h = *(__nv_bfloat162*)&hi;
    return pkrn(x - __bfloat162float(h.x), y - __bfloat162float(h.y));
}
// truncation split: hi = top16(f) exactly, lo = trunc16(f - hi)
__device__ __forceinline__ void pack_trunc2(float a, float b, uint32_t& h, uint32_t& l) {
    uint32_t ba = __float_as_uint(a), bb = __float_as_uint(b);
    h = __byte_perm(ba, bb, 0x7632);
    float ra = a - __uint_as_float(ba & 0xFFFF0000u);
    float rb = b - __uint_as_float(bb & 0xFFFF0000u);
    l = __byte_perm(__float_as_uint(ra), __float_as_uint(rb), 0x7632);
}

__device__ __forceinline__ uint32_t smem_u32(const void* p) {
    uint32_t a;
    asm("{ .reg .u64 t; cvta.to.shared.u64 t, %1; cvt.u32.u64 %0, t; }" : "=r"(a) : "l"(p));
    return a;
}
__device__ __forceinline__ void cpa16(uint32_t dst, const void* src) {
    asm volatile("cp.async.ca.shared.global [%0], [%1], 16;" :: "r"(dst), "l"(src));
}
#define CP_COMMIT() asm volatile("cp.async.commit_group;" ::: "memory")
#define CP_WAIT(n)  asm volatile("cp.async.wait_group %0;" :: "n"(n) : "memory")

// mma.sync m16n8k16 row.col bf16 -> f32 accumulate in place (attention)
__device__ __forceinline__ void mma16816(float* c, const uint32_t* a, uint32_t b0, uint32_t b1) {
    asm volatile(
        "mma.sync.aligned.m16n8k16.row.col.f32.bf16.bf16.f32 "
        "{%0,%1,%2,%3}, {%4,%5,%6,%7}, {%8,%9}, {%0,%1,%2,%3};\n"
        : "+f"(c[0]), "+f"(c[1]), "+f"(c[2]), "+f"(c[3])
        : "r"(a[0]), "r"(a[1]), "r"(a[2]), "r"(a[3]), "r"(b0), "r"(b1));
}

// ---------------- stage 0: sigmoid + transpose of adjacency --------------
__global__ void prep_adj_kernel(const float* __restrict__ logits, float* __restrict__ adjT) {
    int idx = blockIdx.x * 256 + threadIdx.x;
    if (idx >= V_*V_*LP1_) return;
    int s = idx % V_;
    int r = idx / V_;
    int l = r % LP1_;
    int i = r / LP1_;
    float x = logits[(s*V_ + i)*LP1_ + l];
    adjT[idx] = 1.f / (1.f + __expf(-x));
}

// ---------------- weight split (k-major, rounding split) ------------------
__global__ void prep_w_kernel(const float* __restrict__ mW,
                              const float* __restrict__ Wq, const float* __restrict__ Wk,
                              const float* __restrict__ Wv, const float* __restrict__ Wo,
                              __nv_bfloat16* __restrict__ whi, __nv_bfloat16* __restrict__ wlo) {
    int idx = blockIdx.x * 256 + threadIdx.x;      // one float4
    const int per_mat = H_*H_/4;
    if (idx >= 7*V_*per_mat) return;
    int slotmat = idx / per_mat;
    int within  = idx - slotmat * per_mat;
    int s = slotmat >> 6, v = slotmat & 63;
    const float* src;
    if (s < 3)       src = mW + ((size_t)(v*NL_ + s))*H_*H_;
    else if (s == 3) src = Wq + (size_t)v*H_*H_;
    else if (s == 4) src = Wk + (size_t)v*H_*H_;
    else if (s == 5) src = Wv + (size_t)v*H_*H_;
    else             src = Wo + (size_t)v*H_*H_;
    float4 f = *(const float4*)(src + within*4);
    uint32_t h0 = pkrn(f.x, f.y), h1 = pkrn(f.z, f.w);
    uint32_t l0 = pklo(f.x, f.y, h0), l1 = pklo(f.z, f.w, h1);
    size_t o = (size_t)slotmat*H_*H_ + within*4;
    *(uint2*)(whi + o) = make_uint2(h0, h1);
    *(uint2*)(wlo + o) = make_uint2(l0, l1);
}

// ---------------- stage 1: z[b,t,i,h] -------------------------------------
__global__ __launch_bounds__(256)
void stage1_kernel(const float* __restrict__ x, const float* __restrict__ adjT,
                   const float* __restrict__ var_emb, const float* __restrict__ temp_emb,
                   float* __restrict__ z) {
    int bt = blockIdx.x;
    int b = bt >> 8;
    int t = bt & 255;
    __shared__ float xw[LP1_][V_];
    __shared__ float Am[V_][V_ + 1];
    __shared__ float Bls[V_][LP1_ + 1];
    int tid = threadIdx.x;

    for (int p = tid; p < LP1_*V_; p += 256) {
        int l = p / V_, s = p % V_;
        int tt = t - l;
        xw[l][s] = (tt >= 0) ? x[((size_t)(b*S_ + tt))*V_ + s] : 0.f;
    }
    __syncthreads();

    for (int p = tid; p < V_*V_; p += 256) {
        int i = p >> 6, s = p & 63;
        const float* ap = adjT + (size_t)i*LP1_*V_ + s;
        float a = 0.f;
        #pragma unroll
        for (int l = 0; l < LP1_; l++) a += xw[l][s] * ap[l*V_];
        Am[i][s] = a;
    }
    for (int p = tid; p < V_*LP1_; p += 256) {
        int i = p / LP1_, l = p % LP1_;
        const float* ap = adjT + ((size_t)i*LP1_ + l)*V_;
        float a = 0.f;
        #pragma unroll 8
        for (int s = 0; s < V_; s++) a += xw[l][s] * ap[s];
        Bls[i][l] = a;
    }
    __syncthreads();

    int tx = tid & 15, ty = tid >> 4;
    float acc[4][8];
    #pragma unroll
    for (int r = 0; r < 4; r++)
        #pragma unroll
        for (int c = 0; c < 8; c++) acc[r][c] = 0.f;

    for (int s = 0; s < V_; s++) {
        float a0 = Am[ty*4+0][s], a1 = Am[ty*4+1][s], a2 = Am[ty*4+2][s], a3 = Am[ty*4+3][s];
        const float4* vp = (const float4*)(var_emb + (size_t)s*H_ + tx*8);
        float4 v0 = vp[0], v1 = vp[1];
        float bv[8] = {v0.x,v0.y,v0.z,v0.w,v1.x,v1.y,v1.z,v1.w};
        #pragma unroll
        for (int c = 0; c < 8; c++) {
            acc[0][c] += a0*bv[c]; acc[1][c] += a1*bv[c];
            acc[2][c] += a2*bv[c]; acc[3][c] += a3*bv[c];
        }
    }
    #pragma unroll
    for (int l = 0; l < LP1_; l++) {
        float a0 = Bls[ty*4+0][l], a1 = Bls[ty*4+1][l], a2 = Bls[ty*4+2][l], a3 = Bls[ty*4+3][l];
        const float4* vp = (const float4*)(temp_emb + (size_t)l*H_ + tx*8);
        float4 v0 = vp[0], v1 = vp[1];
        float bv[8] = {v0.x,v0.y,v0.z,v0.w,v1.x,v1.y,v1.z,v1.w};
        #pragma unroll
        for (int c = 0; c < 8; c++) {
            acc[0][c] += a0*bv[c]; acc[1][c] += a1*bv[c];
            acc[2][c] += a2*bv[c]; acc[3][c] += a3*bv[c];
        }
    }
    #pragma unroll
    for (int r = 0; r < 4; r++) {
        int i = ty*4 + r;
        float* zp = z + ((size_t)bt*V_ + i)*H_ + tx*8;
        *(float4*)(zp)   = make_float4(acc[r][0], acc[r][1], acc[r][2], acc[r][3]);
        *(float4*)(zp+4) = make_float4(acc[r][4], acc[r][5], acc[r][6], acc[r][7]);
    }
}

// ========= fused GEMM: BM=128, warp tile 32x64, W 32-row cp ring ==========
// smem: 4608(par) + 2*34816(A hi/lo) + 2*17408(W ring) = 109056 -> 2 CTA/SM
#define FP_PAR   0
#define FSA_HI   4608
#define FSA_LO   (FSA_HI + 34816)
#define FSB0     (FSA_LO + 34816)     // buf0: HI 8704 | LO 8704
#define FSB1     (FSB0 + 17408)
#define FGSM     (FSB1 + 17408)       // 109056 B
#define WB_LO    8704
#define FOFF_C   FSB0                 // 32-row fp32 C group buffer (16896 <= 17408)
#define FLDC     132
#define LD2      136   // bf16 elems per smem tile row

// A tile fill: 128 rows x 128 cols fp32 -> bf16 hi/lo smem (truncation split)
__device__ __forceinline__ void fillA(char* smem, const float* __restrict__ src,
                                      size_t rstr, int tid) {
    __nv_bfloat16* aH = (__nv_bfloat16*)(smem + FSA_HI);
    __nv_bfloat16* aL = (__nv_bfloat16*)(smem + FSA_LO);
    #pragma unroll
    for (int i = 0; i < 16; i++) {
        int f = tid + 256*i;
        int row = f >> 5, c4 = f & 31;
        float4 vv = *(const float4*)(src + (size_t)row*rstr + c4*4);
        uint32_t h0, l0, h1, l1;
        pack_trunc2(vv.x, vv.y, h0, l0);
        pack_trunc2(vv.z, vv.w, h1, l1);
        int off = row*LD2 + c4*4;
        *(uint2*)(aH + off) = make_uint2(h0, h1);
        *(uint2*)(aL + off) = make_uint2(l0, l1);
    }
}

// cp.async one 32-row W chunk (hi+lo) into a W buffer
__device__ __forceinline__ void cpW32(uint32_t sb,
                                      const __nv_bfloat16* __restrict__ hi,
                                      const __nv_bfloat16* __restrict__ lo,
                                      int rowbase, int tid) {
    #pragma unroll
    for (int i = 0; i < 2; i++) {
        int f = tid + 256*i;               // 512 segs of 16B
        int row = f >> 4, seg = f & 15;
        uint32_t so = (uint32_t)row*(LD2*2) + seg*16;
        size_t go = (size_t)(rowbase + row)*H_ + seg*8;
        cpa16(sb + so, hi + go);
        cpa16(sb + WB_LO + so, lo + go);
    }
}

// mma over one 32-k chunk; warp tile 32x64: wm=w>>1 (rows wm*32+mi*16),
// wn=w&1 (cols wn*64+ni*16), mi 0..1, ni 0..3
__device__ __forceinline__ void mma_chunk32(char* smem, int sb, int koff,
    int wm, int wn, wmma::fragment<wmma::accumulator,16,16,16,float> (&acc)[2][4]) {
    const __nv_bfloat16* aH = (const __nv_bfloat16*)(smem + FSA_HI);
    const __nv_bfloat16* aL = (const __nv_bfloat16*)(smem + FSA_LO);
    const __nv_bfloat16* bH = (const __nv_bfloat16*)(smem + sb);
    const __nv_bfloat16* bL = (const __nv_bfloat16*)(smem + sb + WB_LO);
    #pragma unroll
    for (int k0 = 0; k0 < 2; k0++) {
        int ka = koff + k0*16;
        wmma::fragment<wmma::matrix_a, 16, 16, 16, __nv_bfloat16, wmma::row_major> afH[2], afL[2];
        wmma::fragment<wmma::matrix_b, 16, 16, 16, __nv_bfloat16, wmma::row_major> bfH[4], bfL[4];
        #pragma unroll
        for (int mi = 0; mi < 2; mi++) {
            wmma::load_matrix_sync(afH[mi], aH + (size_t)(wm*32 + mi*16)*LD2 + ka, LD2);
            wmma::load_matrix_sync(afL[mi], aL + (size_t)(wm*32 + mi*16)*LD2 + ka, LD2);
        }
        #pragma unroll
        for (int ni = 0; ni < 4; ni++) {
            wmma::load_matrix_sync(bfH[ni], bH + (size_t)(k0*16)*LD2 + wn*64 + ni*16, LD2);
            wmma::load_matrix_sync(bfL[ni], bL + (size_t)(k0*16)*LD2 + wn*64 + ni*16, LD2);
        }
        #pragma unroll
        for (int mi = 0; mi < 2; mi++)
            #pragma unroll
            for (int ni = 0; ni < 4; ni++) {
                wmma::mma_sync(acc[mi][ni], afH[mi], bfH[ni], acc[mi][ni]);
                wmma::mma_sync(acc[mi][ni], afH[mi], bfL[ni], acc[mi][ni]);
                wmma::mma_sync(acc[mi][ni], afL[mi], bfH[ni], acc[mi][ni]);
            }
    }
}

// run one layer's mma (ring of 4 32-k chunks); acc left in registers.
__device__ __forceinline__ void run_layer(char* smem, uint32_t sbase,
    const __nv_bfloat16* whi, const __nv_bfloat16* wlo, int wm, int wn, int tid,
    wmma::fragment<wmma::accumulator,16,16,16,float> (&acc)[2][4]) {
    __syncthreads();   // prior epilogue reads of C32 (over FSB0) complete
    #pragma unroll
    for (int mi = 0; mi < 2; mi++)
        #pragma unroll
        for (int ni = 0; ni < 4; ni++) wmma::fill_fragment(acc[mi][ni], 0.f);
    const int bufs[2] = {FSB0, FSB1};
    cpW32(sbase + FSB0, whi, wlo, 0, tid);
    CP_COMMIT();
    #pragma unroll
    for (int c = 0; c < 4; c++) {
        if (c < 3) {
            cpW32(sbase + bufs[(c+1)&1], whi, wlo, (c+1)*32, tid);
            CP_COMMIT();
            CP_WAIT(1);
        } else {
            CP_WAIT(0);
        }
        __syncthreads();
        mma_chunk32(smem, bufs[c&1], c*32, wm, wn, acc);
        __syncthreads();
    }
}

// store the acc fragments of 32-row group g into C32 (warps wm==g)
__device__ __forceinline__ void store_group(char* smem, int g, int wm, int wn,
    wmma::fragment<wmma::accumulator,16,16,16,float> (&acc)[2][4]) {
    if (wm == g) {
        float* Cs = (float*)(smem + FOFF_C);
        #pragma unroll
        for (int mi = 0; mi < 2; mi++)
            #pragma unroll
            for (int ni = 0; ni < 4; ni++)
                wmma::store_matrix_sync(Cs + (size_t)(mi*16)*FLDC + wn*64 + ni*16,
                                        acc[mi][ni], FLDC, wmma::mem_row_major);
    }
}

// ---------------- fused 3-layer mech chain ---------------------------------
__global__ __launch_bounds__(256, 2)
void fused_mech(const float* __restrict__ z, const float* __restrict__ mech_b,
                const float* __restrict__ lng, const float* __restrict__ lnb,
                const __nv_bfloat16* __restrict__ whi, const __nv_bfloat16* __restrict__ wlo,
                float* __restrict__ outz) {
    extern __shared__ char smem[];
    uint32_t sbase = smem_u32(smem);
    int tid = threadIdx.x;
    int v = blockIdx.y, m0 = blockIdx.x * 128;
    int w = tid >> 5, wm = w >> 1, wn = w & 1;

    float* sBias = (float*)(smem + FP_PAR);
    float* sG    = sBias + 3*128;
    float* sBeta = sG + 3*128;
    if (tid < 128) {
        #pragma unroll
        for (int li = 0; li < 3; li++) {
            sBias[li*128 + tid] = mech_b[(size_t)v*NL_*H_ + li*H_ + tid];
            sG[li*128 + tid]    = lng  [(size_t)v*NL_*H_ + li*H_ + tid];
            sBeta[li*128 + tid] = lnb  [(size_t)v*NL_*H_ + li*H_ + tid];
        }
    }
    fillA(smem, z + ((size_t)m0*V_ + v)*H_, (size_t)V_*H_, tid);

    wmma::fragment<wmma::accumulator,16,16,16,float> acc[2][4];
    float* Cs = (float*)(smem + FOFF_C);
    __nv_bfloat16* aH = (__nv_bfloat16*)(smem + FSA_HI);
    __nv_bfloat16* aL = (__nv_bfloat16*)(smem + FSA_LO);
    int row = tid >> 3, seg = tid & 7;   // epilogue: 32 rows x 8 col-segs of 16

    #pragma unroll
    for (int li = 0; li < 3; li++) {
        const __nv_bfloat16* wh = whi + ((size_t)li*V_ + v)*H_*H_;
        const __nv_bfloat16* wl = wlo + ((size_t)li*V_ + v)*H_*H_;
        run_layer(smem, sbase, wh, wl, wm, wn, tid, acc);

        #pragma unroll
        for (int g = 0; g < 4; g++) {
            if (g) __syncthreads();   // C32 reads of prev group done
            store_group(smem, g, wm, wn, acc);
            __syncthreads();
            const float* crow = Cs + (size_t)row*FLDC + seg*16;
            const float* bcol = sBias + li*128 + seg*16;
            float s = 0.f, q = 0.f;
            #pragma unroll
            for (int c = 0; c < 16; c += 4) {
                float4 cc = *(const float4*)(crow + c);
                float4 bb = *(const float4*)(bcol + c);
                float y0 = cc.x+bb.x, y1 = cc.y+bb.y, y2 = cc.z+bb.z, y3 = cc.w+bb.w;
                s += y0 + y1 + y2 + y3;
                q += y0*y0 + y1*y1 + y2*y2 + y3*y3;
            }
            s += __shfl_xor_sync(0xFFFFFFFFu, s, 1);
            q += __shfl_xor_sync(0xFFFFFFFFu, q, 1);
            s += __shfl_xor_sync(0xFFFFFFFFu, s, 2);
            q += __shfl_xor_sync(0xFFFFFFFFu, q, 2);
            s += __shfl_xor_sync(0xFFFFFFFFu, s, 4);
            q += __shfl_xor_sync(0xFFFFFFFFu, q, 4);
            float mean = s * (1.f/128.f);
            float var  = q * (1.f/128.f) - mean*mean;
            float rstd = rsqrtf(var + 1e-5f);
            const float* gcol = sG + li*128 + seg*16;
            const float* lcol = sBeta + li*128 + seg*16;
            int arow = g*32 + row;
            #pragma unroll
            for (int c = 0; c < 16; c += 4) {
                float4 cc = *(const float4*)(crow + c);
                float4 bb = *(const float4*)(bcol + c);
                float4 gg = *(const float4*)(gcol + c);
                float4 ll = *(const float4*)(lcol + c);
                float yv[4] = {cc.x+bb.x, cc.y+bb.y, cc.z+bb.z, cc.w+bb.w};
                float gv[4] = {gg.x, gg.y, gg.z, gg.w};
                float lv[4] = {ll.x, ll.y, ll.z, ll.w};
                float o4[4];
                #pragma unroll
                for (int j = 0; j < 4; j++) {
                    float t2 = (yv[j] - mean) * rstd * gv[j] + lv[j];
                    o4[j] = 0.5f * t2 * (1.f + erff(t2 * 0.7071067811865476f));
                }
                if (li < 2) {
                    uint32_t h0, l0, h1, l1;
                    pack_trunc2(o4[0], o4[1], h0, l0);
                    pack_trunc2(o4[2], o4[3], h1, l1);
                    int off = arow*LD2 + seg*16 + c;
                    *(uint2*)(aH + off) = make_uint2(h0, h1);
                    *(uint2*)(aL + off) = make_uint2(l0, l1);
                } else {
                    *(float4*)(outz + ((size_t)(m0+arow)*V_ + v)*H_ + seg*16 + c) =
                        make_float4(o4[0], o4[1], o4[2], o4[3]);
                }
            }
        }
    }
}

// ---------------- fused QKV (A converted once; 3 weight slots) -------------
__global__ __launch_bounds__(256, 2)
void fused_qkv(const float* __restrict__ z2,
               const __nv_bfloat16* __restrict__ whi, const __nv_bfloat16* __restrict__ wlo,
               float* __restrict__ qkv) {
    extern __shared__ char smem[];
    uint32_t sbase = smem_u32(smem);
    int tid = threadIdx.x;
    int v = blockIdx.y, m0 = blockIdx.x * 128;
    int w = tid >> 5, wm = w >> 1, wn = w & 1;

    fillA(smem, z2 + ((size_t)m0*V_ + v)*H_, (size_t)V_*H_, tid);

    wmma::fragment<wmma::accumulator,16,16,16,float> acc[2][4];
    float* Cs = (float*)(smem + FOFF_C);
    int row = tid >> 3, seg = tid & 7;

    #pragma unroll
    for (int zi = 0; zi < 3; zi++) {
        const __nv_bfloat16* wh = whi + ((size_t)(3+zi)*V_ + v)*H_*H_;
        const __nv_bfloat16* wl = wlo + ((size_t)(3+zi)*V_ + v)*H_*H_;
        run_layer(smem, sbase, wh, wl, wm, wn, tid, acc);
        #pragma unroll
        for (int g = 0; g < 4; g++) {
            if (g) __syncthreads();
            store_group(smem, g, wm, wn, acc);
            __syncthreads();
            float* orow = qkv + (size_t)zi*M_*V_*H_
                        + ((size_t)(m0 + g*32 + row)*V_ + v)*H_ + seg*16;
            const float* crow = Cs + (size_t)row*FLDC + seg*16;
            #pragma unroll
            for (int c = 0; c < 16; c += 4)
                *(float4*)(orow + c) = *(const float4*)(crow + c);
        }
    }
}

// ---------------- O-proj + output head -------------------------------------
__global__ __launch_bounds__(256, 2)
void oproj_gemm(const float* __restrict__ att,
                const __nv_bfloat16* __restrict__ whi, const __nv_bfloat16* __restrict__ wlo,
                const float* __restrict__ bo, const float* __restrict__ oW,
                const float* __restrict__ oB, float* __restrict__ out) {
    extern __shared__ char smem[];
    uint32_t sbase = smem_u32(smem);
    int tid = threadIdx.x;
    int v = blockIdx.y, m0 = blockIdx.x * 128;
    int w = tid >> 5, wm = w >> 1, wn = w & 1;

    float* sBias = (float*)(smem + FP_PAR);
    float* sG    = sBias + 3*128;
    if (tid < 128) {
        sBias[tid] = bo[(size_t)v*H_ + tid];
        sG[tid]    = oW[(size_t)v*H_ + tid];
    }
    fillA(smem, att + ((size_t)m0*V_ + v)*H_, (size_t)V_*H_, tid);

    wmma::fragment<wmma::accumulator,16,16,16,float> acc[2][4];
    const __nv_bfloat16* wh = whi + ((size_t)6*V_ + v)*H_*H_;
    const __nv_bfloat16* wl = wlo + ((size_t)6*V_ + v)*H_*H_;
    run_layer(smem, sbase, wh, wl, wm, wn, tid, acc);

    float* Cs = (float*)(smem + FOFF_C);
    int row = tid >> 3, seg = tid & 7;
    #pragma unroll
    for (int g = 0; g < 4; g++) {
        if (g) __syncthreads();
        store_group(smem, g, wm, wn, acc);
        __syncthreads();
        const float* crow = Cs + (size_t)row*FLDC + seg*16;
        const float* bcol = sBias + seg*16;
        const float* gcol = sG + seg*16;
        float p = 0.f;
        #pragma unroll
        for (int c = 0; c < 16; c += 4) {
            float4 cc = *(const float4*)(crow + c);
            float4 bb = *(const float4*)(bcol + c);
            float4 gg = *(const float4*)(gcol + c);
            p += (cc.x+bb.x)*gg.x + (cc.y+bb.y)*gg.y + (cc.z+bb.z)*gg.z + (cc.w+bb.w)*gg.w;
        }
        p += __shfl_xor_sync(0xFFFFFFFFu, p, 1);
        p += __shfl_xor_sync(0xFFFFFFFFu, p, 2);
        p += __shfl_xor_sync(0xFFFFFFFFu, p, 4);
        if (seg == 0)
            out[(size_t)(m0 + g*32 + row)*V_ + v] = p + oB[v];
    }
}

// ================= flash-style mma attention ===============================
#define KSTR 12
#define VSTR 132

__global__ __launch_bounds__(256)
void attn_mma(const float* __restrict__ qkv,
              const float* __restrict__ bq, const float* __restrict__ bk,
              const float* __restrict__ bv, float* __restrict__ out) {
    __shared__ uint32_t khi[256*KSTR], klo[256*KSTR];
    __shared__ uint32_t vthi[16*VSTR], vtlo[16*VSTR];

    int bid = blockIdx.x;
    int n = bid & 7, v = (bid >> 3) & 63, b = bid >> 9;
    int tid = threadIdx.x, w = tid >> 5, lane = tid & 31;

    const float* q  = qkv;
    const float* kk = qkv + (size_t)M_*V_*H_;
    const float* vv = qkv + 2*(size_t)M_*V_*H_;
    size_t rstr = (size_t)V_*H_;
    size_t base = ((size_t)(b*S_)*V_ + v)*H_ + n*DH_;
    size_t bofs = (size_t)v*H_ + n*DH_;

    {
        int key = tid;
        const float4* kp = (const float4*)(kk + base + (size_t)key*rstr);
        const float4* vp = (const float4*)(vv + base + (size_t)key*rstr);
        float kr[16], vr[16];
        #pragma unroll
        for (int i = 0; i < 4; i++) {
            float4 a = kp[i], c = vp[i];
            float4 bb = *(const float4*)(bk + bofs + i*4);
            float4 cb = *(const float4*)(bv + bofs + i*4);
            kr[i*4+0]=a.x+bb.x; kr[i*4+1]=a.y+bb.y; kr[i*4+2]=a.z+bb.z; kr[i*4+3]=a.w+bb.w;
            vr[i*4+0]=c.x+cb.x; vr[i*4+1]=c.y+cb.y; vr[i*4+2]=c.z+cb.z; vr[i*4+3]=c.w+cb.w;
        }
        #pragma unroll
        for (int d = 0; d < 8; d++) {
            uint32_t h = pkrn(kr[2*d], kr[2*d+1]);
            khi[key*KSTR + d] = h;
            klo[key*KSTR + d] = pklo(kr[2*d], kr[2*d+1], h);
        }
        unsigned short* vthi16 = (unsigned short*)vthi;
        unsigned short* vtlo16 = (unsigned short*)vtlo;
        #pragma unroll
        for (int c = 0; c < 16; c++) {
            __nv_bfloat16 hb = __float2bfloat16(vr[c]);
            float lo = vr[c] - __bfloat162float(hb);
            __nv_bfloat16 lb = __float2bfloat16(lo);
            vthi16[c*(2*VSTR) + key] = __bfloat16_as_ushort(hb);
            vtlo16[c*(2*VSTR) + key] = __bfloat16_as_ushort(lb);
        }
    }

    int rq = w*32 + (lane >> 2);
    int c2 = (lane & 3) * 2;
    float2 bq0 = make_float2(bq[bofs + c2],     bq[bofs + c2 + 1]);
    float2 bq1 = make_float2(bq[bofs + c2 + 8], bq[bofs + c2 + 9]);
    uint32_t qhi[2][4], qlo[2][4];
    #pragma unroll
    for (int mi = 0; mi < 2; mi++) {
        int rA = rq + mi*16, rB = rA + 8;
        float2 x00 = *(const float2*)(q + base + (size_t)rA*rstr + c2);
        float2 x01 = *(const float2*)(q + base + (size_t)rA*rstr + c2 + 8);
        float2 x10 = *(const float2*)(q + base + (size_t)rB*rstr + c2);
        float2 x11 = *(const float2*)(q + base + (size_t)rB*rstr + c2 + 8);
        x00.x = (x00.x + bq0.x)*0.25f; x00.y = (x00.y + bq0.y)*0.25f;
        x01.x = (x01.x + bq1.x)*0.25f; x01.y = (x01.y + bq1.y)*0.25f;
        x10.x = (x10.x + bq0.x)*0.25f; x10.y = (x10.y + bq0.y)*0.25f;
        x11.x = (x11.x + bq1.x)*0.25f; x11.y = (x11.y + bq1.y)*0.25f;
        qhi[mi][0] = pkrn(x00.x, x00.y); qlo[mi][0] = pklo(x00.x, x00.y, qhi[mi][0]);
        qhi[mi][1] = pkrn(x10.x, x10.y); qlo[mi][1] = pklo(x10.x, x10.y, qhi[mi][1]);
        qhi[mi][2] = pkrn(x01.x, x01.y); qlo[mi][2] = pklo(x01.x, x01.y, qhi[mi][2]);
        qhi[mi][3] = pkrn(x11.x, x11.y); qlo[mi][3] = pklo(x11.x, x11.y, qhi[mi][3]);
    }
    __syncthreads();

    float oacc[2][2][4];
    #pragma unroll
    for (int mi = 0; mi < 2; mi++)
        #pragma unroll
        for (int d = 0; d < 2; d++)
            #pragma unroll
            for (int e = 0; e < 4; e++) oacc[mi][d][e] = 0.f;
    float mrun[2][2] = {{-1e30f,-1e30f},{-1e30f,-1e30f}};
    float lrun[2][2] = {{0.f,0.f},{0.f,0.f}};

    #pragma unroll
    for (int kt = 0; kt < 4; kt++) {
        int kb = kt * 64;
        uint32_t sbh[8][2], sbl[8][2];
        #pragma unroll
        for (int j = 0; j < 8; j++) {
            int key = kb + j*8 + (lane >> 2);
            int ci  = lane & 3;
            sbh[j][0] = khi[key*KSTR + ci];     sbh[j][1] = khi[key*KSTR + ci + 4];
            sbl[j][0] = klo[key*KSTR + ci];     sbl[j][1] = klo[key*KSTR + ci + 4];
        }
        #pragma unroll
        for (int mi = 0; mi < 2; mi++) {
            float C[8][4];
            #pragma unroll
            for (int j = 0; j < 8; j++) { C[j][0]=0.f; C[j][1]=0.f; C[j][2]=0.f; C[j][3]=0.f; }
            #pragma unroll
            for (int j = 0; j < 8; j++) {
                mma16816(C[j], qhi[mi], sbh[j][0], sbh[j][1]);
                mma16816(C[j], qhi[mi], sbl[j][0], sbl[j][1]);
                mma16816(C[j], qlo[mi], sbh[j][0], sbh[j][1]);
            }
            float mA = -1e30f, mB = -1e30f;
            #pragma unroll
            for (int j = 0; j < 8; j++) {
                mA = fmaxf(mA, fmaxf(C[j][0], C[j][1]));
                mB = fmaxf(mB, fmaxf(C[j][2], C[j][3]));
            }
            mA = fmaxf(mA, __shfl_xor_sync(0xFFFFFFFFu, mA, 1));
            mA = fmaxf(mA, __shfl_xor_sync(0xFFFFFFFFu, mA, 2));
            mB = fmaxf(mB, __shfl_xor_sync(0xFFFFFFFFu, mB, 1));
            mB = fmaxf(mB, __shfl_xor_sync(0xFFFFFFFFu, mB, 2));
            float nA = fmaxf(mrun[mi][0], mA), nB = fmaxf(mrun[mi][1], mB);
            float cA = __expf(mrun[mi][0] - nA), cB = __expf(mrun[mi][1] - nB);
            mrun[mi][0] = nA; mrun[mi][1] = nB;
            float sA = 0.f, sB = 0.f;
            #pragma unroll
            for (int j = 0; j < 8; j++) {
                C[j][0] = __expf(C[j][0] - nA); C[j][1] = __expf(C[j][1] - nA);
                C[j][2] = __expf(C[j][2] - nB); C[j][3] = __expf(C[j][3] - nB);
                sA += C[j][0] + C[j][1];
                sB += C[j][2] + C[j][3];
            }
            sA += __shfl_xor_sync(0xFFFFFFFFu, sA, 1);
            sA += __shfl_xor_sync(0xFFFFFFFFu, sA, 2);
            sB += __shfl_xor_sync(0xFFFFFFFFu, sB, 1);
            sB += __shfl_xor_sync(0xFFFFFFFFu, sB, 2);
            lrun[mi][0] = lrun[mi][0]*cA + sA;
            lrun[mi][1] = lrun[mi][1]*cB + sB;
            #pragma unroll
            for (int d = 0; d < 2; d++) {
                oacc[mi][d][0] *= cA; oacc[mi][d][1] *= cA;
                oacc[mi][d][2] *= cB; oacc[mi][d][3] *= cB;
            }
            #pragma unroll
            for (int u = 0; u < 4; u++) {
                uint32_t pa[4], pl[4];
                pa[0] = pkrn(C[2*u][0],   C[2*u][1]);   pl[0] = pklo(C[2*u][0],   C[2*u][1],   pa[0]);
                pa[1] = pkrn(C[2*u][2],   C[2*u][3]);   pl[1] = pklo(C[2*u][2],   C[2*u][3],   pa[1]);
                pa[2] = pkrn(C[2*u+1][0], C[2*u+1][1]); pl[2] = pklo(C[2*u+1][0], C[2*u+1][1], pa[2]);
                pa[3] = pkrn(C[2*u+1][2], C[2*u+1][3]); pl[3] = pklo(C[2*u+1][2], C[2*u+1][3], pa[3]);
                int kb2h = (kb + u*16) >> 1;
                #pragma unroll
                for (int d = 0; d < 2; d++) {
                    int nrow = d*8 + (lane >> 2);
                    uint32_t b0h = vthi[nrow*VSTR + kb2h + (lane & 3)];
                    uint32_t b1h = vthi[nrow*VSTR + kb2h + 4 + (lane & 3)];
                    uint32_t b0l = vtlo[nrow*VSTR + kb2h + (lane & 3)];
                    uint32_t b1l = vtlo[nrow*VSTR + kb2h + 4 + (lane & 3)];
                    mma16816(oacc[mi][d], pa, b0h, b1h);
                    mma16816(oacc[mi][d], pa, b0l, b1l);
                    mma16816(oacc[mi][d], pl, b0h, b1h);
                }
            }
        }
    }

    #pragma unroll
    for (int mi = 0; mi < 2; mi++) {
        float iA = 1.f / lrun[mi][0], iB = 1.f / lrun[mi][1];
        int rA = w*32 + mi*16 + (lane >> 2), rB = rA + 8;
        #pragma unroll
        for (int d = 0; d < 2; d++) {
            *(float2*)(out + base + (size_t)rA*rstr + d*8 + c2) =
                make_float2(oacc[mi][d][0]*iA, oacc[mi][d][1]*iA);
            *(float2*)(out + base + (size_t)rB*rstr + d*8 + c2) =
                make_float2(oacc[mi][d][2]*iB, oacc[mi][d][3]*iB);
        }
    }
}

// ---------------- launch ---------------------------------------------------
extern "C" void kernel_launch(void* const* d_in, const int* in_sizes, int n_in,
                              void* d_out, int out_size) {
    const float* x       = (const float*)d_in[0];
    const float* adjlog  = (const float*)d_in[1];
    const float* var_emb = (const float*)d_in[2];
    const float* temp_emb= (const float*)d_in[3];
    const float* mech_W  = (const float*)d_in[4];
    const float* mech_b  = (const float*)d_in[5];
    const float* ln_g    = (const float*)d_in[6];
    const float* ln_b    = (const float*)d_in[7];
    const float* Wq      = (const float*)d_in[8];
    const float* Wk      = (const float*)d_in[9];
    const float* Wv      = (const float*)d_in[10];
    const float* Wo      = (const float*)d_in[11];
    const float* bq      = (const float*)d_in[12];
    const float* bk      = (const float*)d_in[13];
    const float* bv      = (const float*)d_in[14];
    const float* bo      = (const float*)d_in[15];
    const float* out_W   = (const float*)d_in[16];
    const float* out_b   = (const float*)d_in[17];
    float* out = (float*)d_out;

    float *adjT, *z, *z2, *qkv;
    __nv_bfloat16 *whi, *wlo;
    cudaGetSymbolAddress((void**)&adjT, g_adjT);
    cudaGetSymbolAddress((void**)&z,    g_z);
    cudaGetSymbolAddress((void**)&z2,   g_z2);
    cudaGetSymbolAddress((void**)&qkv,  g_qkv);
    cudaGetSymbolAddress((void**)&whi,  g_whi);
    cudaGetSymbolAddress((void**)&wlo,  g_wlo);

    cudaFuncSetAttribute(fused_mech, cudaFuncAttributeMaxDynamicSharedMemorySize, FGSM);
    cudaFuncSetAttribute(fused_qkv,  cudaFuncAttributeMaxDynamicSharedMemorySize, FGSM);
    cudaFuncSetAttribute(oproj_gemm, cudaFuncAttributeMaxDynamicSharedMemorySize, FGSM);

    prep_adj_kernel<<<(V_*V_*LP1_ + 255)/256, 256>>>(adjlog, adjT);
    prep_w_kernel<<<(7*V_*H_*H_/4 + 255)/256, 256>>>(mech_W, Wq, Wk, Wv, Wo, whi, wlo);
    stage1_kernel<<<M_, 256>>>(x, adjT, var_emb, temp_emb, z);

    dim3 gg(M_/128, V_);
    fused_mech<<<gg, 256, FGSM>>>(z, mech_b, ln_g, ln_b, whi, wlo, z2);
    fused_qkv<<<gg, 256, FGSM>>>(z2, whi, wlo, qkv);
    attn_mma<<<B_*V_*NH_, 256>>>(qkv, bq, bk, bv, z);
    oproj_gemm<<<gg, 256, FGSM>>>(z, whi, wlo, bo, out_W, out_b, out);
}